// round 4
// baseline (speedup 1.0000x reference)
#include <cuda_runtime.h>

// ---------------------------------------------------------------------------
// ChordProgressionLoss v4 — coalesced lane=row layout + all-integer core.
//   pc bits via double-magic-FADD (no cvt, no LOP): pc = low5(b1 - 12*b2).
//   Jaccard window terms as exact bytes 60*i/(p+3-i) packed into one u32 per
//   row (1 broadcast LDS + PRMT); window sums = 3 shfl + PRMT gather + dp4a;
//   min(maj,mino) -> integer max. Sim as fixed-point (it*R30+A30, LDS.64).
//   All sums are exact integers -> cross-block atomics are deterministic.
//   Warp = two 29-row chunks, 4 front-batched LDG.128 for MLP.
// ---------------------------------------------------------------------------

#define WPB 8
#define THREADS (WPB * 32)

__device__ unsigned long long g_simSlots[32];
__device__ unsigned long long g_penSlots[32];
__device__ unsigned int       g_count = 0;

__device__ __forceinline__ unsigned pcbit(float f) {
    unsigned b1 = __float_as_uint(f + 12582912.0f);            // low bits = iv
    float t = fmaf(f, 0.0833333358f, -0.45833334f);            // iv/12 - 0.4583
    unsigned b2 = __float_as_uint(t + 12582912.0f);            // low bits = floor(iv/12)
    unsigned x = b1 - 12u * b2;                                // low5 = iv mod 12
    return 1u << (x & 31u);
}
__device__ __forceinline__ unsigned pcmask(float4 v) {
    return pcbit(v.x) | pcbit(v.y) | pcbit(v.z) | pcbit(v.w);
}
// {a.b0, b.b1, c.b2, d.b3}
__device__ __forceinline__ unsigned win4(unsigned a, unsigned b, unsigned c, unsigned d) {
    unsigned p1 = __byte_perm(a, b, 0x0050);
    unsigned p2 = __byte_perm(c, d, 0x0072);
    return __byte_perm(p1, p2, 0x5410);
}

__device__ __forceinline__ void doChunk(
    float4 pv, float4 tv, int r, int T, int lane,
    const unsigned* __restrict__ sT60, const uint2* __restrict__ sSim,
    unsigned long long& simAcc, unsigned& penAcc)
{
    unsigned pm = pcmask(pv);
    unsigned tm = pcmask(tv);
    int p  = __popc(pm);                      // 1..4
    int q  = __popc(tm);
    int it = __popc(pm & tm);

    bool own = (lane < 29) && (r < T);
    uint2 ra = sSim[p * 4 + q];
    if (own) simAcc += (unsigned long long)((unsigned)it * ra.x + ra.y);

    unsigned Tp = sT60[p];                    // 4 jaccard bytes for this p
    unsigned selM = (unsigned)__popc(pm & 0x091u) * 0x1001u
                  | ((unsigned)__popc(pm & 0x221u) << 4)
                  | ((unsigned)__popc(pm & 0x884u) << 8);
    unsigned selm = (unsigned)__popc(pm & 0x089u) * 0x1001u
                  | ((unsigned)__popc(pm & 0x121u) << 4)
                  | ((unsigned)__popc(pm & 0x484u) << 8);
    unsigned BM = __byte_perm(Tp, 0, selM);   // {tM0, tM1, tM2, tM0}
    unsigned Bm = __byte_perm(Tp, 0, selm);

    unsigned M1 = __shfl_down_sync(0xffffffffu, BM, 1);
    unsigned M2 = __shfl_down_sync(0xffffffffu, BM, 2);
    unsigned M3 = __shfl_down_sync(0xffffffffu, BM, 3);
    unsigned m1 = __shfl_down_sync(0xffffffffu, Bm, 1);
    unsigned m2 = __shfl_down_sync(0xffffffffu, Bm, 2);
    unsigned m3 = __shfl_down_sync(0xffffffffu, Bm, 3);

    unsigned SM = __dp4a(win4(BM, M1, M2, M3), 0x01010101u, 0u);
    unsigned Sm = __dp4a(win4(Bm, m1, m2, m3), 0x01010101u, 0u);
    if (own && (r <= T - 4)) penAcc += (SM > Sm) ? SM : Sm;   // 240*(1-min)
}

__global__ __launch_bounds__(THREADS) void chord_fused(
    const float4* __restrict__ pred, const float4* __restrict__ targ,
    float* __restrict__ out, int T, int nWarps)
{
    __shared__ unsigned sT60[5];   // [p] bytes {60*i/(p+3-i)}, i=0..3
    __shared__ uint2    sSim[21];  // [p*4+q] = {R30, A30}
    __shared__ bool     sLast;

    const int tid = threadIdx.x;
    if (tid < 5) {
        int p = tid; unsigned w = 0;
        for (int i = 0; i < 4; i++) {
            int dnm = p + 3 - i;
            unsigned t = (dnm > 0) ? (unsigned)((60 * i) / dnm) : 0u;
            w |= (t & 0xFFu) << (8 * i);
        }
        sT60[p] = w;
    }
    if (tid < 16) {
        int p = (tid >> 2) + 1, q = (tid & 3) + 1;
        double r = 1.0 / (((double)p + 12e-6) * ((double)q + 12e-6));
        unsigned R30 = (unsigned)__double2ll_rn(r * 1073741824.0);
        unsigned A30 = (unsigned)__double2ll_rn((1e-6 * (p + q) + 1.2e-11) * r * 1073741824.0);
        sSim[p * 4 + q] = make_uint2(R30, A30);
    }
    __syncthreads();

    const int lane = tid & 31;
    const int wid  = tid >> 5;
    const int wg   = blockIdx.x * WPB + wid;

    unsigned long long simAcc = 0ull;
    unsigned penAcc = 0u;

    if (wg < nWarps) {
        const int base = wg * 58;
        const int rA = base + lane;
        const int rB = base + 29 + lane;
        const float4 z = make_float4(0.f, 0.f, 0.f, 0.f);
        float4 pA = z, tA = z, pB = z, tB = z;
        // front-batched coalesced loads (4x LDG.128 in flight)
        if (rA < T) { pA = pred[rA]; tA = targ[rA]; }
        if (rB < T) { pB = pred[rB]; tB = targ[rB]; }

        doChunk(pA, tA, rA, T, lane, sT60, sSim, simAcc, penAcc);
        doChunk(pB, tB, rB, T, lane, sT60, sSim, simAcc, penAcc);
    }

    // warp reduction (exact integers -> order-independent)
    unsigned long long penW = (unsigned long long)penAcc;
    #pragma unroll
    for (int o = 16; o; o >>= 1) {
        simAcc += __shfl_xor_sync(0xffffffffu, simAcc, o);
        penW   += __shfl_xor_sync(0xffffffffu, penW,   o);
    }
    if (lane == 0 && wg < nWarps) {
        int slot = wg & 31;
        atomicAdd(&g_simSlots[slot], simAcc);
        atomicAdd(&g_penSlots[slot], penW);
    }
    __syncthreads();
    if (tid == 0) {
        __threadfence();
        sLast = (atomicAdd(&g_count, 1u) == gridDim.x - 1);
    }
    __syncthreads();

    if (sLast && tid < 32) {
        __threadfence();
        unsigned long long s = *(volatile unsigned long long*)&g_simSlots[tid];
        unsigned long long p = *(volatile unsigned long long*)&g_penSlots[tid];
        #pragma unroll
        for (int o = 16; o; o >>= 1) {
            s += __shfl_xor_sync(0xffffffffu, s, o);
            p += __shfl_xor_sync(0xffffffffu, p, o);
        }
        if (tid == 0) {
            double simMean = ((double)s * (1.0 / 1073741824.0)) / (double)T;
            long long nWin = (long long)T - 3;
            double pen = (nWin > 0) ? (0.5 - (double)p / (480.0 * (double)nWin)) : 0.0;
            out[0] = (float)((1.0 - simMean) + pen);
        }
        g_simSlots[tid] = 0ull;    // self-reset for graph replay
        g_penSlots[tid] = 0ull;
        if (tid == 0) g_count = 0;
    }
}

extern "C" void kernel_launch(void* const* d_in, const int* in_sizes, int n_in,
                              void* d_out, int out_size)
{
    const float4* pred = (const float4*)d_in[0];
    const float4* targ = (const float4*)d_in[1];
    int T1 = in_sizes[0] / 4;
    int T2 = in_sizes[1] / 4;
    int T = (T1 < T2) ? T1 : T2;

    int nWarps = (T + 57) / 58;            // warp = two 29-row chunks
    if (nWarps < 1) nWarps = 1;
    int blocks = (nWarps + WPB - 1) / WPB;

    chord_fused<<<blocks, THREADS>>>(pred, targ, (float*)d_out, T, nWarps);
}

// round 5
// speedup vs baseline: 1.5594x; 1.5594x over previous
#include <cuda_runtime.h>

// ---------------------------------------------------------------------------
// ChordProgressionLoss v5 — R4 integer core + MINIMUM BLOCK COUNT.
// Diagnosis across R2-R4: dur ~ 4us + 9ns/block (same-address g_count atomic
// serializes on the critical path). Fix: 296 blocks x 1024 threads (full
// occupancy, 64 warps/SM) -> epilogue/atomic instances cut 7x.
// Core: coalesced lane=row LDG.128, masks via double-magic-FADD, jaccard
// bytes via PRMT + dp4a windows, integer max for min(maj,mino), fixed-point
// sim. Exact integer sums -> atomics deterministic.
// ---------------------------------------------------------------------------

#define NBLK 296
#define THREADS 1024
#define WPB 32

__device__ unsigned long long g_simSlots[32];
__device__ unsigned long long g_penSlots[32];
__device__ unsigned int       g_count = 0;

__device__ __forceinline__ unsigned pcbit(float f) {
    unsigned b1 = __float_as_uint(f + 12582912.0f);          // low bits = iv
    float t = fmaf(f, 0.0833333358f, -0.45833334f);
    unsigned b2 = __float_as_uint(t + 12582912.0f);          // low bits = iv/12
    unsigned x = b1 - 12u * b2;                              // low5 = iv%12
    return 1u << (x & 31u);
}
__device__ __forceinline__ unsigned pcmask(float4 v) {
    return pcbit(v.x) | pcbit(v.y) | pcbit(v.z) | pcbit(v.w);
}
// {a.b0, b.b1, c.b2, d.b3}
__device__ __forceinline__ unsigned win4(unsigned a, unsigned b, unsigned c, unsigned d) {
    unsigned p1 = __byte_perm(a, b, 0x0050);
    unsigned p2 = __byte_perm(c, d, 0x0072);
    return __byte_perm(p1, p2, 0x5410);
}

__device__ __forceinline__ void doChunk(
    float4 pv, float4 tv, int r, int T, int lane,
    const unsigned* __restrict__ sT60, const uint2* __restrict__ sSim,
    unsigned long long& simAcc, unsigned& penAcc)
{
    unsigned pm = pcmask(pv);
    unsigned tm = pcmask(tv);
    int p  = __popc(pm);                      // 1..4
    int q  = __popc(tm);
    int it = __popc(pm & tm);

    bool own = (lane < 29) && (r < T);
    uint2 ra = sSim[p * 4 + q];
    if (own) simAcc += (unsigned long long)((unsigned)it * ra.x + ra.y);

    unsigned Tp = sT60[p];
    unsigned selM = (unsigned)__popc(pm & 0x091u) * 0x1001u
                  | ((unsigned)__popc(pm & 0x221u) << 4)
                  | ((unsigned)__popc(pm & 0x884u) << 8);
    unsigned selm = (unsigned)__popc(pm & 0x089u) * 0x1001u
                  | ((unsigned)__popc(pm & 0x121u) << 4)
                  | ((unsigned)__popc(pm & 0x484u) << 8);
    unsigned BM = __byte_perm(Tp, 0, selM);   // {tM0,tM1,tM2,tM0}
    unsigned Bm = __byte_perm(Tp, 0, selm);

    unsigned M1 = __shfl_down_sync(0xffffffffu, BM, 1);
    unsigned M2 = __shfl_down_sync(0xffffffffu, BM, 2);
    unsigned M3 = __shfl_down_sync(0xffffffffu, BM, 3);
    unsigned m1 = __shfl_down_sync(0xffffffffu, Bm, 1);
    unsigned m2 = __shfl_down_sync(0xffffffffu, Bm, 2);
    unsigned m3 = __shfl_down_sync(0xffffffffu, Bm, 3);

    unsigned SM = __dp4a(win4(BM, M1, M2, M3), 0x01010101u, 0u);
    unsigned Sm = __dp4a(win4(Bm, m1, m2, m3), 0x01010101u, 0u);
    if (own && (r <= T - 4)) penAcc += (SM > Sm) ? SM : Sm;   // 240*(1-min)
}

__global__ __launch_bounds__(THREADS, 2) void chord_fused(
    const float4* __restrict__ pred, const float4* __restrict__ targ,
    float* __restrict__ out, int T, int nUnits)
{
    __shared__ unsigned sT60[5];
    __shared__ uint2    sSim[21];
    __shared__ unsigned long long redS[WPB], redP[WPB];
    __shared__ bool     sLast;

    const int tid = threadIdx.x;
    if (tid < 5) {
        int p = tid; unsigned w = 0;
        for (int i = 0; i < 4; i++) {
            int dnm = p + 3 - i;
            unsigned t = (dnm > 0) ? (unsigned)((60 * i) / dnm) : 0u;
            w |= (t & 0xFFu) << (8 * i);
        }
        sT60[p] = w;
    }
    if (tid < 16) {
        int p = (tid >> 2) + 1, q = (tid & 3) + 1;
        double r = 1.0 / (((double)p + 12e-6) * ((double)q + 12e-6));
        unsigned R30 = (unsigned)__double2ll_rn(r * 1073741824.0);
        unsigned A30 = (unsigned)__double2ll_rn((1e-6 * (p + q) + 1.2e-11) * r * 1073741824.0);
        sSim[p * 4 + q] = make_uint2(R30, A30);
    }
    __syncthreads();

    const int lane = tid & 31;
    const int wid  = tid >> 5;

    unsigned long long simAcc = 0ull;
    unsigned penAcc = 0u;
    const float4 z = make_float4(0.f, 0.f, 0.f, 0.f);

    // grid-stride over 58-row superchunks (two 29-row windows each)
    for (int u = blockIdx.x * WPB + wid; u < nUnits; u += gridDim.x * WPB) {
        const int base = u * 58;
        const int rA = base + lane;
        const int rB = base + 29 + lane;
        float4 pA = z, tA = z, pB = z, tB = z;
        if (rA < T) { pA = pred[rA]; tA = targ[rA]; }   // 4x LDG.128 batched
        if (rB < T) { pB = pred[rB]; tB = targ[rB]; }

        doChunk(pA, tA, rA, T, lane, sT60, sSim, simAcc, penAcc);
        doChunk(pB, tB, rB, T, lane, sT60, sSim, simAcc, penAcc);
    }

    // warp reduction (exact integers)
    unsigned long long penW = (unsigned long long)penAcc;
    #pragma unroll
    for (int o = 16; o; o >>= 1) {
        simAcc += __shfl_xor_sync(0xffffffffu, simAcc, o);
        penW   += __shfl_xor_sync(0xffffffffu, penW,   o);
    }
    if (lane == 0) { redS[wid] = simAcc; redP[wid] = penW; }
    __syncthreads();

    // block reduction by warp 0, then ONE pair of slot atomics + one counter
    if (wid == 0) {
        unsigned long long s = redS[lane];
        unsigned long long p = redP[lane];
        #pragma unroll
        for (int o = 16; o; o >>= 1) {
            s += __shfl_xor_sync(0xffffffffu, s, o);
            p += __shfl_xor_sync(0xffffffffu, p, o);
        }
        if (lane == 0) {
            int slot = blockIdx.x & 31;
            atomicAdd(&g_simSlots[slot], s);
            atomicAdd(&g_penSlots[slot], p);
            __threadfence();
            sLast = (atomicAdd(&g_count, 1u) == gridDim.x - 1);
        }
    }
    __syncthreads();

    // last block: deterministic final reduce of 32+32 slots, write, reset
    if (sLast && wid == 0) {
        __threadfence();
        unsigned long long s = *(volatile unsigned long long*)&g_simSlots[lane];
        unsigned long long p = *(volatile unsigned long long*)&g_penSlots[lane];
        #pragma unroll
        for (int o = 16; o; o >>= 1) {
            s += __shfl_xor_sync(0xffffffffu, s, o);
            p += __shfl_xor_sync(0xffffffffu, p, o);
        }
        if (lane == 0) {
            double simMean = ((double)s * (1.0 / 1073741824.0)) / (double)T;
            long long nWin = (long long)T - 3;
            double pen = (nWin > 0) ? (0.5 - (double)p / (480.0 * (double)nWin)) : 0.0;
            out[0] = (float)((1.0 - simMean) + pen);
        }
        g_simSlots[lane] = 0ull;   // self-reset for graph replay
        g_penSlots[lane] = 0ull;
        if (lane == 0) g_count = 0;
    }
}

extern "C" void kernel_launch(void* const* d_in, const int* in_sizes, int n_in,
                              void* d_out, int out_size)
{
    const float4* pred = (const float4*)d_in[0];
    const float4* targ = (const float4*)d_in[1];
    int T1 = in_sizes[0] / 4;
    int T2 = in_sizes[1] / 4;
    int T = (T1 < T2) ? T1 : T2;

    int nUnits = (T + 57) / 58;
    if (nUnits < 1) nUnits = 1;
    int blocks = (nUnits + WPB - 1) / WPB;
    if (blocks > NBLK) blocks = NBLK;

    chord_fused<<<blocks, THREADS>>>(pred, targ, (float*)d_out, T, nUnits);
}